// round 1
// baseline (speedup 1.0000x reference)
#include <cuda_runtime.h>
#include <math.h>

#define Nn   100000
#define Ee   1600000
#define Fin  128
#define Hh   64
#define Cc   40
#define NB_SCAN ((Nn + 1023) / 1024)

// ---------------- scratch (static device globals; no runtime alloc) -------
__device__ float g_bufA[Nn * Hh];
__device__ float g_bufB[Nn * Hh];
__device__ float g_xn  [Nn * Hh];
__device__ float g_nrm [Nn];
__device__ int   g_deg [Nn];
__device__ int   g_rowptr[Nn + 1];
__device__ int   g_pos [Nn];
__device__ int   g_col [Ee];
__device__ int   g_bsums[NB_SCAN];

// ---------------- helpers --------------------------------------------------
__device__ __forceinline__ float warp_sum(float v) {
    #pragma unroll
    for (int o = 16; o > 0; o >>= 1) v += __shfl_xor_sync(0xffffffffu, v, o);
    return v;
}
__device__ __forceinline__ float warp_max(float v) {
    #pragma unroll
    for (int o = 16; o > 0; o >>= 1) v = fmaxf(v, __shfl_xor_sync(0xffffffffu, v, o));
    return v;
}

// ---------------- CSR build -------------------------------------------------
__global__ void k_init_deg() {
    int i = blockIdx.x * blockDim.x + threadIdx.x;
    if (i < Nn) g_deg[i] = 0;
}

__global__ void k_hist(const int* __restrict__ edge_index) {
    int e = blockIdx.x * blockDim.x + threadIdx.x;
    if (e < Ee) atomicAdd(&g_deg[edge_index[Ee + e]], 1);
}

__global__ void k_scan1() {
    __shared__ int s[1024];
    int t = threadIdx.x;
    int idx = blockIdx.x * 1024 + t;
    int v = (idx < Nn) ? g_deg[idx] : 0;
    s[t] = v;
    __syncthreads();
    #pragma unroll
    for (int off = 1; off < 1024; off <<= 1) {
        int x = (t >= off) ? s[t - off] : 0;
        __syncthreads();
        s[t] += x;
        __syncthreads();
    }
    int incl = s[t];
    if (idx < Nn) g_rowptr[idx] = incl - v;   // exclusive (block-local)
    if (t == 1023) g_bsums[blockIdx.x] = incl;
}

__global__ void k_scan2() {
    if (threadIdx.x == 0 && blockIdx.x == 0) {
        int running = 0;
        for (int b = 0; b < NB_SCAN; b++) {
            int v = g_bsums[b];
            g_bsums[b] = running;
            running += v;
        }
    }
}

__global__ void k_scan3() {
    int i = blockIdx.x * blockDim.x + threadIdx.x;
    if (i < Nn) {
        int v = g_rowptr[i] + g_bsums[i >> 10];
        g_rowptr[i] = v;
        g_pos[i] = v;
    }
    if (i == 0) g_rowptr[Nn] = Ee;
}

__global__ void k_scatter(const int* __restrict__ edge_index) {
    int e = blockIdx.x * blockDim.x + threadIdx.x;
    if (e < Ee) {
        int d = edge_index[Ee + e];
        int p = atomicAdd(&g_pos[d], 1);
        g_col[p] = edge_index[e];
    }
}

// ---------------- GEMM1: h = relu(x @ W1 + b1), [N,128]x[128,64] ----------
__global__ void k_gemm1(const float* __restrict__ x, const float* __restrict__ W1,
                        const float* __restrict__ b1) {
    __shared__ float Ws[Fin * Hh];       // 32 KB
    __shared__ float As[16][68];         // transposed x tile, padded
    int t = threadIdx.x;                  // 256 threads
    int row0 = blockIdx.x * 64;
    for (int i = t; i < Fin * Hh; i += 256) Ws[i] = W1[i];

    int tx = t & 15;   // cols tx*4 .. tx*4+3
    int ty = t >> 4;   // rows ty*4 .. ty*4+3
    float acc[4][4] = {};

    for (int k0 = 0; k0 < Fin; k0 += 16) {
        __syncthreads();
        {
            int c = t & 15, r = t >> 4;
            #pragma unroll
            for (int i = 0; i < 4; i++) {
                int rr = r + i * 16;
                int grow = row0 + rr;
                As[c][rr] = (grow < Nn) ? x[grow * Fin + k0 + c] : 0.f;
            }
        }
        __syncthreads();
        #pragma unroll
        for (int kk = 0; kk < 16; kk++) {
            float4 a = *(const float4*)&As[kk][ty * 4];
            float4 w = *(const float4*)&Ws[(k0 + kk) * Hh + tx * 4];
            acc[0][0] += a.x * w.x; acc[0][1] += a.x * w.y; acc[0][2] += a.x * w.z; acc[0][3] += a.x * w.w;
            acc[1][0] += a.y * w.x; acc[1][1] += a.y * w.y; acc[1][2] += a.y * w.z; acc[1][3] += a.y * w.w;
            acc[2][0] += a.z * w.x; acc[2][1] += a.z * w.y; acc[2][2] += a.z * w.z; acc[2][3] += a.z * w.w;
            acc[3][0] += a.w * w.x; acc[3][1] += a.w * w.y; acc[3][2] += a.w * w.z; acc[3][3] += a.w * w.w;
        }
    }
    float4 bb = *(const float4*)&b1[tx * 4];
    #pragma unroll
    for (int r = 0; r < 4; r++) {
        int grow = row0 + ty * 4 + r;
        if (grow < Nn) {
            float4 o;
            o.x = fmaxf(acc[r][0] + bb.x, 0.f);
            o.y = fmaxf(acc[r][1] + bb.y, 0.f);
            o.z = fmaxf(acc[r][2] + bb.z, 0.f);
            o.w = fmaxf(acc[r][3] + bb.w, 0.f);
            *(float4*)&g_bufA[grow * Hh + tx * 4] = o;
        }
    }
}

// ---------------- per-layer normalize: xn = h/max(||h||,eps), nrm = ||h|| --
__global__ void k_normalize(int srcA) {
    int gt = blockIdx.x * blockDim.x + threadIdx.x;
    int node = gt >> 5;
    int lane = gt & 31;
    if (node >= Nn) return;
    const float* h = srcA ? g_bufA : g_bufB;
    float2 v = ((const float2*)h)[node * 32 + lane];
    float ss = warp_sum(v.x * v.x + v.y * v.y);
    float nrm = sqrtf(ss);
    float inv = 1.f / fmaxf(nrm, 1e-12f);
    float2 o; o.x = v.x * inv; o.y = v.y * inv;
    ((float2*)g_xn)[node * 32 + lane] = o;
    if (lane == 0) g_nrm[node] = nrm;
}

// ---------------- AGNN layer: warp per dst node, fused softmax+aggregate ---
// alpha = exp(cos)/sum exp(cos)  (max-shift unnecessary: |cos| <= 1)
// h[src] reconstructed as xn[src]*nrm[src]  (single row load per edge)
__global__ void k_agnn(int srcA) {
    int gt = blockIdx.x * blockDim.x + threadIdx.x;
    int node = gt >> 5;
    int lane = gt & 31;
    if (node >= Nn) return;
    float* out = srcA ? g_bufB : g_bufA;
    const float2* xn2 = (const float2*)g_xn;

    float2 xd = xn2[node * 32 + lane];
    float nd = g_nrm[node];

    // implicit self loop
    float d = warp_sum(xd.x * xd.x + xd.y * xd.y);
    float w = __expf(d);
    float s = w;
    float c0 = w * nd;
    float ax = c0 * xd.x, ay = c0 * xd.y;

    int beg = g_rowptr[node], end = g_rowptr[node + 1];
    for (int j = beg; j < end; j++) {
        int src = g_col[j];                 // uniform across warp -> broadcast
        float2 xs = xn2[src * 32 + lane];
        float t = warp_sum(xd.x * xs.x + xd.y * xs.y);
        float ww = __expf(t);
        float c = ww * g_nrm[src];
        s += ww;
        ax += c * xs.x;
        ay += c * xs.y;
    }
    float invs = 1.f / s;
    float2 o; o.x = ax * invs; o.y = ay * invs;
    ((float2*)out)[node * 32 + lane] = o;
}

// ---------------- GEMM2 + log_softmax, warp per row ------------------------
__global__ void k_gemm2_lsm(const float* __restrict__ W2, const float* __restrict__ b2,
                            float* __restrict__ out) {
    __shared__ float W2s[Hh * Cc + 32];   // padded (lanes 8..31 read garbage, masked)
    __shared__ float b2s[64];
    int t = threadIdx.x;                   // 256 threads, 8 warps
    for (int i = t; i < Hh * Cc; i += 256) W2s[i] = W2[i];
    if (t < 64) b2s[t] = (t < Cc) ? b2[t] : 0.f;
    __syncthreads();

    int row = blockIdx.x * 8 + (t >> 5);
    int l = t & 31;
    if (row >= Nn) return;
    const float* hr = g_bufA + row * Hh;   // final buffer after 4 layers

    float a0 = 0.f, a1 = 0.f;
    #pragma unroll 8
    for (int k = 0; k < Hh; k++) {
        float hk = hr[k];                  // uniform across warp -> broadcast
        a0 += hk * W2s[k * Cc + l];
        a1 += hk * W2s[k * Cc + 32 + l];   // only valid for l < 8
    }
    float v0 = a0 + b2s[l];
    float v1 = a1 + b2s[32 + l];

    float m = v0;
    if (l < 8) m = fmaxf(m, v1);
    m = warp_max(m);
    float e = __expf(v0 - m) + ((l < 8) ? __expf(v1 - m) : 0.f);
    float se = warp_sum(e);
    float ls = m + logf(se);
    out[row * Cc + l] = v0 - ls;
    if (l < 8) out[row * Cc + 32 + l] = v1 - ls;
}

// ---------------- launch ----------------------------------------------------
extern "C" void kernel_launch(void* const* d_in, const int* in_sizes, int n_in,
                              void* d_out, int out_size) {
    const float* x   = (const float*)d_in[0];
    const float* W1  = (const float*)d_in[1];
    const float* b1  = (const float*)d_in[2];
    const float* W2  = (const float*)d_in[3];
    const float* b2  = (const float*)d_in[4];
    const int* eidx  = (const int*)d_in[5];
    float* out = (float*)d_out;

    // CSR by dst
    k_init_deg<<<(Nn + 255) / 256, 256>>>();
    k_hist<<<(Ee + 255) / 256, 256>>>(eidx);
    k_scan1<<<NB_SCAN, 1024>>>();
    k_scan2<<<1, 32>>>();
    k_scan3<<<(Nn + 255) / 256, 256>>>();
    k_scatter<<<(Ee + 255) / 256, 256>>>(eidx);

    // h = relu(x@W1+b1) -> bufA
    k_gemm1<<<(Nn + 63) / 64, 256>>>(x, W1, b1);

    // 4 AGNN layers, ping-pong A<->B (ends in A)
    int srcA = 1;
    for (int layer = 0; layer < 4; layer++) {
        k_normalize<<<(Nn * 32 + 255) / 256, 256>>>(srcA);
        k_agnn<<<(Nn * 32 + 255) / 256, 256>>>(srcA);
        srcA ^= 1;
    }

    // out = log_softmax(h@W2+b2)
    k_gemm2_lsm<<<(Nn + 7) / 8, 256>>>(W2, b2, out);
}

// round 2
// speedup vs baseline: 1.2048x; 1.2048x over previous
#include <cuda_runtime.h>
#include <math.h>

#define Nn   100000
#define Ee   1600000
#define Fin  128
#define Hh   64
#define Cc   40
#define NB_SCAN ((Nn + 1023) / 1024)

// ---------------- scratch (static device globals; no runtime alloc) -------
__device__ float g_bufA[Nn * Hh];     // final h for gemm2
__device__ float g_xnA [Nn * Hh];
__device__ float g_xnB [Nn * Hh];
__device__ float g_nrmA[Nn];
__device__ float g_nrmB[Nn];
__device__ int   g_deg [Nn];
__device__ int   g_rowptr[Nn + 1];
__device__ int   g_pos [Nn];
__device__ int   g_col [Ee];
__device__ int   g_bsums[NB_SCAN];

// ---------------- helpers --------------------------------------------------
__device__ __forceinline__ float warp_sum(float v) {
    #pragma unroll
    for (int o = 16; o > 0; o >>= 1) v += __shfl_xor_sync(0xffffffffu, v, o);
    return v;
}
__device__ __forceinline__ float warp_max(float v) {
    #pragma unroll
    for (int o = 16; o > 0; o >>= 1) v = fmaxf(v, __shfl_xor_sync(0xffffffffu, v, o));
    return v;
}
// reduce across a converged 16-lane half (mask selects the half)
__device__ __forceinline__ float red16(float v, unsigned m) {
    v += __shfl_xor_sync(m, v, 1);
    v += __shfl_xor_sync(m, v, 2);
    v += __shfl_xor_sync(m, v, 4);
    v += __shfl_xor_sync(m, v, 8);
    return v;
}

// ---------------- CSR build -------------------------------------------------
__global__ void k_init_deg() {
    int i = blockIdx.x * blockDim.x + threadIdx.x;
    if (i < Nn) g_deg[i] = 0;
}

__global__ void k_hist(const int* __restrict__ edge_index) {
    int e = blockIdx.x * blockDim.x + threadIdx.x;
    if (e < Ee) atomicAdd(&g_deg[edge_index[Ee + e]], 1);
}

__global__ void k_scan1() {
    __shared__ int s[1024];
    int t = threadIdx.x;
    int idx = blockIdx.x * 1024 + t;
    int v = (idx < Nn) ? g_deg[idx] : 0;
    s[t] = v;
    __syncthreads();
    #pragma unroll
    for (int off = 1; off < 1024; off <<= 1) {
        int x = (t >= off) ? s[t - off] : 0;
        __syncthreads();
        s[t] += x;
        __syncthreads();
    }
    int incl = s[t];
    if (idx < Nn) g_rowptr[idx] = incl - v;   // exclusive (block-local)
    if (t == 1023) g_bsums[blockIdx.x] = incl;
}

// parallel scan of 98 block sums (one 128-thread block)
__global__ void k_scan2() {
    __shared__ int s[128];
    int t = threadIdx.x;
    int v = (t < NB_SCAN) ? g_bsums[t] : 0;
    s[t] = v;
    __syncthreads();
    #pragma unroll
    for (int off = 1; off < 128; off <<= 1) {
        int x = (t >= off) ? s[t - off] : 0;
        __syncthreads();
        s[t] += x;
        __syncthreads();
    }
    if (t < NB_SCAN) g_bsums[t] = s[t] - v;   // exclusive
}

__global__ void k_scan3() {
    int i = blockIdx.x * blockDim.x + threadIdx.x;
    if (i < Nn) {
        int v = g_rowptr[i] + g_bsums[i >> 10];
        g_rowptr[i] = v;
        g_pos[i] = v;
    }
    if (i == 0) g_rowptr[Nn] = Ee;
}

__global__ void k_scatter(const int* __restrict__ edge_index) {
    int e = blockIdx.x * blockDim.x + threadIdx.x;
    if (e < Ee) {
        int d = edge_index[Ee + e];
        int p = atomicAdd(&g_pos[d], 1);
        g_col[p] = edge_index[e];
    }
}

// ---------------- GEMM1 fused normalize: xnA,nrmA = normalize(relu(x@W1+b1))
__global__ void k_gemm1(const float* __restrict__ x, const float* __restrict__ W1,
                        const float* __restrict__ b1) {
    __shared__ float Ws[Fin * Hh];       // 32 KB
    __shared__ float As[16][68];         // transposed x tile, padded
    int t = threadIdx.x;                  // 256 threads
    int row0 = blockIdx.x * 64;
    for (int i = t; i < Fin * Hh; i += 256) Ws[i] = W1[i];

    int tx = t & 15;   // cols tx*4 .. tx*4+3
    int ty = t >> 4;   // rows ty*4 .. ty*4+3
    float acc[4][4] = {};

    for (int k0 = 0; k0 < Fin; k0 += 16) {
        __syncthreads();
        {
            int c = t & 15, r = t >> 4;
            #pragma unroll
            for (int i = 0; i < 4; i++) {
                int rr = r + i * 16;
                int grow = row0 + rr;
                As[c][rr] = (grow < Nn) ? x[grow * Fin + k0 + c] : 0.f;
            }
        }
        __syncthreads();
        #pragma unroll
        for (int kk = 0; kk < 16; kk++) {
            float4 a = *(const float4*)&As[kk][ty * 4];
            float4 w = *(const float4*)&Ws[(k0 + kk) * Hh + tx * 4];
            acc[0][0] += a.x * w.x; acc[0][1] += a.x * w.y; acc[0][2] += a.x * w.z; acc[0][3] += a.x * w.w;
            acc[1][0] += a.y * w.x; acc[1][1] += a.y * w.y; acc[1][2] += a.y * w.z; acc[1][3] += a.y * w.w;
            acc[2][0] += a.z * w.x; acc[2][1] += a.z * w.y; acc[2][2] += a.z * w.z; acc[2][3] += a.z * w.w;
            acc[3][0] += a.w * w.x; acc[3][1] += a.w * w.y; acc[3][2] += a.w * w.z; acc[3][3] += a.w * w.w;
        }
    }
    float4 bb = *(const float4*)&b1[tx * 4];
    // bias + relu, then fused row-normalize: the 16 threads sharing ty hold row
    // row0+ty*4+r; they are a converged 16-lane half-warp (lane = (ty&1)*16+tx).
    unsigned hm = 0xffffu << ((ty & 1) * 16);
    #pragma unroll
    for (int r = 0; r < 4; r++) {
        float4 o;
        o.x = fmaxf(acc[r][0] + bb.x, 0.f);
        o.y = fmaxf(acc[r][1] + bb.y, 0.f);
        o.z = fmaxf(acc[r][2] + bb.z, 0.f);
        o.w = fmaxf(acc[r][3] + bb.w, 0.f);
        float ss = red16(o.x * o.x + o.y * o.y + o.z * o.z + o.w * o.w, hm);
        float nrm = sqrtf(ss);
        float inv = 1.f / fmaxf(nrm, 1e-12f);
        int grow = row0 + ty * 4 + r;
        if (grow < Nn) {
            float4 xo; xo.x = o.x * inv; xo.y = o.y * inv; xo.z = o.z * inv; xo.w = o.w * inv;
            *(float4*)&g_xnA[grow * Hh + tx * 4] = xo;
            if (tx == 0) g_nrmA[grow] = nrm;
        }
    }
}

// ---------------- AGNN layer: warp per dst node, half-warp per edge --------
// alpha = exp(cos)/sum exp(cos)  (max-shift unnecessary: |cos| <= 1)
// h[src] = xn[src]*nrm[src]. Fused epilogue normalize of the output row
// (ping-pong xnA<->xnB); final layer writes raw h to g_bufA instead.
__global__ void k_agnn(int inA, int last) {
    int gt = blockIdx.x * blockDim.x + threadIdx.x;
    int node = gt >> 5;
    int lane = gt & 31;
    if (node >= Nn) return;

    const float* __restrict__ xn_in  = inA ? g_xnA : g_xnB;
    const float* __restrict__ nrm_in = inA ? g_nrmA : g_nrmB;
    float* __restrict__ xn_out  = inA ? g_xnB : g_xnA;
    float* __restrict__ nrm_out = inA ? g_nrmB : g_nrmA;

    int hh = lane >> 4;               // which edge of the pair
    int c  = lane & 15;               // float4 chunk (4 dims)
    unsigned hm = 0xffffu << (hh * 16);

    float4 xd = *(const float4*)&xn_in[node * Hh + c * 4];

    // self loop (counted once, in half 0)
    float d = red16(xd.x * xd.x + xd.y * xd.y + xd.z * xd.z + xd.w * xd.w,
                    0xffffffffu >> ((1 - hh) * 16) << (hh * 16));
    float w = __expf(d);
    float nd = nrm_in[node];
    float sh = 0.f;
    float4 acc = make_float4(0.f, 0.f, 0.f, 0.f);
    if (hh == 0) {
        sh = w;
        float cs = w * nd;
        acc.x = cs * xd.x; acc.y = cs * xd.y; acc.z = cs * xd.z; acc.w = cs * xd.w;
    }

    int beg = g_rowptr[node];
    int nE  = g_rowptr[node + 1] - beg;
    for (int it = hh; it < nE; it += 2) {
        int src = g_col[beg + it];                        // broadcast within half
        float4 xs = *(const float4*)&xn_in[src * Hh + c * 4];
        float tt = red16(xd.x * xs.x + xd.y * xs.y + xd.z * xs.z + xd.w * xs.w, hm);
        float ww = __expf(tt);
        float cs = ww * nrm_in[src];
        sh += ww;
        acc.x += cs * xs.x; acc.y += cs * xs.y; acc.z += cs * xs.z; acc.w += cs * xs.w;
    }
    __syncwarp();

    // combine the two halves (same dims in both)
    float s = sh + __shfl_xor_sync(0xffffffffu, sh, 16);
    acc.x += __shfl_xor_sync(0xffffffffu, acc.x, 16);
    acc.y += __shfl_xor_sync(0xffffffffu, acc.y, 16);
    acc.z += __shfl_xor_sync(0xffffffffu, acc.z, 16);
    acc.w += __shfl_xor_sync(0xffffffffu, acc.w, 16);

    float invs = 1.f / s;
    float4 o;
    o.x = acc.x * invs; o.y = acc.y * invs; o.z = acc.z * invs; o.w = acc.w * invs;

    if (last) {
        if (hh == 0) *(float4*)&g_bufA[node * Hh + c * 4] = o;
    } else {
        // fused normalize of the output row
        float ss = red16(o.x * o.x + o.y * o.y + o.z * o.z + o.w * o.w, hm);
        float nrm = sqrtf(ss);
        float inv = 1.f / fmaxf(nrm, 1e-12f);
        if (hh == 0) {
            float4 xo; xo.x = o.x * inv; xo.y = o.y * inv; xo.z = o.z * inv; xo.w = o.w * inv;
            *(float4*)&xn_out[node * Hh + c * 4] = xo;
            if (c == 0) nrm_out[node] = nrm;
        }
    }
}

// ---------------- GEMM2 + log_softmax, warp per row ------------------------
__global__ void k_gemm2_lsm(const float* __restrict__ W2, const float* __restrict__ b2,
                            float* __restrict__ out) {
    __shared__ float W2s[Hh * Cc + 32];   // padded (lanes 8..31 read garbage, masked)
    __shared__ float b2s[64];
    int t = threadIdx.x;                   // 256 threads, 8 warps
    for (int i = t; i < Hh * Cc; i += 256) W2s[i] = W2[i];
    if (t < 64) b2s[t] = (t < Cc) ? b2[t] : 0.f;
    __syncthreads();

    int row = blockIdx.x * 8 + (t >> 5);
    int l = t & 31;
    if (row >= Nn) return;
    const float* hr = g_bufA + row * Hh;

    float a0 = 0.f, a1 = 0.f;
    #pragma unroll 8
    for (int k = 0; k < Hh; k++) {
        float hk = hr[k];                  // uniform across warp -> broadcast
        a0 += hk * W2s[k * Cc + l];
        a1 += hk * W2s[k * Cc + 32 + l];   // only valid for l < 8
    }
    float v0 = a0 + b2s[l];
    float v1 = a1 + b2s[32 + l];

    float m = v0;
    if (l < 8) m = fmaxf(m, v1);
    m = warp_max(m);
    float e = __expf(v0 - m) + ((l < 8) ? __expf(v1 - m) : 0.f);
    float se = warp_sum(e);
    float ls = m + logf(se);
    out[row * Cc + l] = v0 - ls;
    if (l < 8) out[row * Cc + 32 + l] = v1 - ls;
}

// ---------------- launch ----------------------------------------------------
extern "C" void kernel_launch(void* const* d_in, const int* in_sizes, int n_in,
                              void* d_out, int out_size) {
    const float* x   = (const float*)d_in[0];
    const float* W1  = (const float*)d_in[1];
    const float* b1  = (const float*)d_in[2];
    const float* W2  = (const float*)d_in[3];
    const float* b2  = (const float*)d_in[4];
    const int* eidx  = (const int*)d_in[5];
    float* out = (float*)d_out;

    // CSR by dst
    k_init_deg<<<(Nn + 255) / 256, 256>>>();
    k_hist<<<(Ee + 255) / 256, 256>>>(eidx);
    k_scan1<<<NB_SCAN, 1024>>>();
    k_scan2<<<1, 128>>>();
    k_scan3<<<(Nn + 255) / 256, 256>>>();
    k_scatter<<<(Ee + 255) / 256, 256>>>(eidx);

    // h = relu(x@W1+b1) fused normalize -> xnA, nrmA
    k_gemm1<<<(Nn + 63) / 64, 256>>>(x, W1, b1);

    // 4 AGNN layers, xn ping-pong A->B->A->B, last writes h -> bufA
    int inA = 1;
    for (int layer = 0; layer < 4; layer++) {
        k_agnn<<<(Nn * 32 + 255) / 256, 256>>>(inA, layer == 3);
        inA ^= 1;
    }

    // out = log_softmax(h@W2+b2)
    k_gemm2_lsm<<<(Nn + 7) / 8, 256>>>(W2, b2, out);
}